// round 3
// baseline (speedup 1.0000x reference)
#include <cuda_runtime.h>
#include <cstdint>

#define BROWS 4096
#define INF   1024
#define OUTF  1024
#define KDIM  9216          // INF * 9  (silu + 8 basis columns per input feature)
#define CHUNK 32
#define ITERS 288           // KDIM / CHUNK
#define STAGES 4
#define SROW  36            // smem row stride in floats (conflict-free fragment loads)
#define TILE_BYTES  (128 * SROW * 4)     // 18432 per operand tile
#define STAGE_BYTES (2 * TILE_BYTES)     // 36864
#define SMEM_TOTAL  (STAGES * STAGE_BYTES)  // 147456

// Scratch (static device globals — no runtime allocation)
__device__ __align__(256) float g_act[(size_t)BROWS * KDIM];  // [4096, 9216]
__device__ __align__(256) float g_w[(size_t)OUTF * KDIM];     // [1024, 9216]

__device__ __forceinline__ float tf32r(float x) {
    asm("cvt.rna.tf32.f32 %0, %1;" : "=f"(x) : "f"(x));
    return x;
}

// ---------------------------------------------------------------------------
// Kernel 1: activation matrix.  Act[b, i*9+0] = silu(x), [.. +1+q] = basis_q(x)
// ---------------------------------------------------------------------------
__global__ __launch_bounds__(256) void act_kernel(const float* __restrict__ x,
                                                  const float* __restrict__ grid) {
    int idx = blockIdx.x * 256 + threadIdx.x;   // b*1024 + i
    float xv = x[idx];
    float g[12];
#pragma unroll
    for (int j = 0; j < 12; j++) g[j] = __ldg(grid + j);

    float bas[11];
#pragma unroll
    for (int j = 0; j < 11; j++) bas[j] = (xv >= g[j] && xv < g[j + 1]) ? 1.f : 0.f;
#pragma unroll
    for (int k = 1; k <= 3; k++) {
#pragma unroll
        for (int j = 0; j + k <= 10; j++) {
            float left  = (xv - g[j]) / (g[j + k] - g[j] + 1e-8f);
            float right = (g[j + k + 1] - xv) / (g[j + k + 1] - g[j + 1] + 1e-8f);
            bas[j] = left * bas[j] + right * bas[j + 1];
        }
    }
    float s = xv / (1.f + __expf(-xv));

    float* o = g_act + (size_t)idx * 9;   // b*9216 + i*9 == 9*idx
    o[0] = tf32r(s);
#pragma unroll
    for (int q = 0; q < 8; q++) o[1 + q] = tf32r(bas[q]);
}

// ---------------------------------------------------------------------------
// Kernel 2: weight matrix.  W[o, i*9+0]=bw[o,i], [.. +1+q]=sw[o,i,q]
// ---------------------------------------------------------------------------
__global__ __launch_bounds__(256) void wconv_kernel(const float* __restrict__ bw,
                                                    const float* __restrict__ sw) {
    int idx = blockIdx.x * 256 + threadIdx.x;   // o*1024 + i
    float* o = g_w + (size_t)idx * 9;
    o[0] = tf32r(bw[idx]);
    const float4* sp = (const float4*)(sw + (size_t)idx * 8);
    float4 a = sp[0], b = sp[1];
    o[1] = tf32r(a.x); o[2] = tf32r(a.y); o[3] = tf32r(a.z); o[4] = tf32r(a.w);
    o[5] = tf32r(b.x); o[6] = tf32r(b.y); o[7] = tf32r(b.z); o[8] = tf32r(b.w);
}

// ---------------------------------------------------------------------------
// Kernel 3: tf32 mma.sync GEMM  out[4096,1024] = Act @ W^T
// CTA tile 128x128, 256 threads = 8 warps (2m x 4n), warp tile 64x32.
// 4-stage cp.async pipeline, smem stride 36 floats (conflict-free frags).
// ---------------------------------------------------------------------------
__device__ __forceinline__ void issue_stage(uint32_t sb, int stage, int it,
                                            int m0, int n0, int tid) {
    const int kk = it * CHUNK;
    const uint32_t sA = sb + stage * STAGE_BYTES;
    const uint32_t sB = sA + TILE_BYTES;
#pragma unroll
    for (int j = 0; j < 4; j++) {
        int id  = tid + j * 256;
        int row = id >> 3, c = id & 7;
        const float* ga = &g_act[(size_t)(m0 + row) * KDIM + kk + c * 4];
        asm volatile("cp.async.cg.shared.global [%0], [%1], 16;"
                     :: "r"(sA + (uint32_t)(row * SROW + c * 4) * 4), "l"(ga));
        const float* gb = &g_w[(size_t)(n0 + row) * KDIM + kk + c * 4];
        asm volatile("cp.async.cg.shared.global [%0], [%1], 16;"
                     :: "r"(sB + (uint32_t)(row * SROW + c * 4) * 4), "l"(gb));
    }
}

__global__ __launch_bounds__(256, 1) void gemm_kernel(float* __restrict__ out) {
    extern __shared__ __align__(16) char smem[];
    const uint32_t sb = (uint32_t)__cvta_generic_to_shared(smem);
    const int tid = threadIdx.x;
    const int wid = tid >> 5, lane = tid & 31;
    const int g = lane >> 2, t = lane & 3;         // quad group / thread-in-group
    const int wm = wid >> 2, wn = wid & 3;         // 2 x 4 warp grid
    const int m0 = blockIdx.y * 128, n0 = blockIdx.x * 128;

    float acc[4][4][4];
#pragma unroll
    for (int i = 0; i < 4; i++)
#pragma unroll
        for (int j = 0; j < 4; j++)
#pragma unroll
            for (int r = 0; r < 4; r++) acc[i][j][r] = 0.f;

#pragma unroll
    for (int s = 0; s < STAGES - 1; s++) {
        issue_stage(sb, s, s, m0, n0, tid);
        asm volatile("cp.async.commit_group;");
    }

    const int aRow = wm * 64 + g;       // base A row for this lane
    const int bRow = wn * 32 + g;       // base B row for this lane

    for (int it = 0; it < ITERS; ++it) {
        asm volatile("cp.async.wait_group %0;" :: "n"(STAGES - 2));
        __syncthreads();
        if (it + STAGES - 1 < ITERS)
            issue_stage(sb, (it + STAGES - 1) % STAGES, it + STAGES - 1, m0, n0, tid);
        asm volatile("cp.async.commit_group;");

        const int buf = it % STAGES;
        const float* As = (const float*)(smem + buf * STAGE_BYTES);
        const float* Bs = (const float*)(smem + buf * STAGE_BYTES + TILE_BYTES);

#pragma unroll
        for (int kb = 0; kb < CHUNK; kb += 8) {
            float af[4][4], bf[4][2];
#pragma unroll
            for (int mi = 0; mi < 4; mi++) {
                int r = aRow + mi * 16;
                af[mi][0] = As[r * SROW + kb + t];
                af[mi][1] = As[(r + 8) * SROW + kb + t];
                af[mi][2] = As[r * SROW + kb + t + 4];
                af[mi][3] = As[(r + 8) * SROW + kb + t + 4];
            }
#pragma unroll
            for (int ni = 0; ni < 4; ni++) {
                int r = bRow + ni * 8;
                bf[ni][0] = Bs[r * SROW + kb + t];
                bf[ni][1] = Bs[r * SROW + kb + t + 4];
            }
#pragma unroll
            for (int mi = 0; mi < 4; mi++)
#pragma unroll
                for (int ni = 0; ni < 4; ni++) {
                    asm volatile(
                        "mma.sync.aligned.m16n8k8.row.col.f32.tf32.tf32.f32 "
                        "{%0,%1,%2,%3}, {%4,%5,%6,%7}, {%8,%9}, {%0,%1,%2,%3};"
                        : "+f"(acc[mi][ni][0]), "+f"(acc[mi][ni][1]),
                          "+f"(acc[mi][ni][2]), "+f"(acc[mi][ni][3])
                        : "r"(__float_as_uint(af[mi][0])), "r"(__float_as_uint(af[mi][1])),
                          "r"(__float_as_uint(af[mi][2])), "r"(__float_as_uint(af[mi][3])),
                          "r"(__float_as_uint(bf[ni][0])), "r"(__float_as_uint(bf[ni][1])));
                }
        }
    }

    // Epilogue: direct STG (each quad writes 32B contiguous segments)
#pragma unroll
    for (int mi = 0; mi < 4; mi++)
#pragma unroll
        for (int ni = 0; ni < 4; ni++) {
            int row = m0 + wm * 64 + mi * 16 + g;
            int col = n0 + wn * 32 + ni * 8 + 2 * t;
            float2 v0 = make_float2(acc[mi][ni][0], acc[mi][ni][1]);
            float2 v1 = make_float2(acc[mi][ni][2], acc[mi][ni][3]);
            *(float2*)&out[(size_t)row * OUTF + col]       = v0;
            *(float2*)&out[(size_t)(row + 8) * OUTF + col] = v1;
        }
}

// ---------------------------------------------------------------------------
extern "C" void kernel_launch(void* const* d_in, const int* in_sizes, int n_in,
                              void* d_out, int out_size) {
    const float* x    = (const float*)d_in[0];
    const float* bw   = (const float*)d_in[1];
    const float* sw   = (const float*)d_in[2];
    const float* grid = (const float*)d_in[3];
    float* out = (float*)d_out;

    cudaFuncSetAttribute(gemm_kernel, cudaFuncAttributeMaxDynamicSharedMemorySize,
                         SMEM_TOTAL);

    act_kernel<<<(BROWS * INF) / 256, 256>>>(x, grid);
    wconv_kernel<<<(OUTF * INF) / 256, 256>>>(bw, sw);
    gemm_kernel<<<dim3(OUTF / 128, BROWS / 128), 256, SMEM_TOTAL>>>(out);
}

// round 4
// speedup vs baseline: 1.5565x; 1.5565x over previous
#include <cuda_runtime.h>
#include <cuda_fp16.h>
#include <cstdint>

#define BROWS 4096
#define INF   1024
#define OUTF  1024
#define KDIM  9216          // INF * 9  (silu + 8 basis columns per input feature)
#define CHUNK 32            // k-chunk in halfs (64 B rows)
#define ITERS 288           // KDIM / CHUNK
#define STAGES 4
#define SROW_H 40           // smem row stride in halfs (80 B, conflict-free frags)
#define TILE_BYTES  (128 * SROW_H * 2)   // 10240 per operand tile
#define STAGE_BYTES (2 * TILE_BYTES)     // 20480
#define SMEM_TOTAL  (STAGES * STAGE_BYTES)  // 81920

// Scratch (static device globals — no runtime allocation)
__device__ __align__(256) __half g_act[(size_t)BROWS * KDIM];  // [4096, 9216]
__device__ __align__(256) __half g_w[(size_t)OUTF * KDIM];     // [1024, 9216]

// ---------------------------------------------------------------------------
// Kernel 1: activation matrix.  Act[b, i*9+0] = silu(x), [.. +1+q] = basis_q(x)
// Coalesced via smem staging: block of 256 threads -> 2304 contiguous halfs.
// ---------------------------------------------------------------------------
__global__ __launch_bounds__(256) void act_kernel(const float* __restrict__ x,
                                                  const float* __restrict__ grid) {
    __shared__ __half sbuf[256 * 9];
    int tid = threadIdx.x;
    int idx = blockIdx.x * 256 + tid;   // b*1024 + i
    float xv = x[idx];
    float g[12];
#pragma unroll
    for (int j = 0; j < 12; j++) g[j] = __ldg(grid + j);

    float bas[11];
#pragma unroll
    for (int j = 0; j < 11; j++) bas[j] = (xv >= g[j] && xv < g[j + 1]) ? 1.f : 0.f;
#pragma unroll
    for (int k = 1; k <= 3; k++) {
#pragma unroll
        for (int j = 0; j + k <= 10; j++) {
            float left  = (xv - g[j]) / (g[j + k] - g[j] + 1e-8f);
            float right = (g[j + k + 1] - xv) / (g[j + k + 1] - g[j + 1] + 1e-8f);
            bas[j] = left * bas[j] + right * bas[j + 1];
        }
    }
    float s = xv / (1.f + __expf(-xv));

    sbuf[tid * 9] = __float2half_rn(s);
#pragma unroll
    for (int q = 0; q < 8; q++) sbuf[tid * 9 + 1 + q] = __float2half_rn(bas[q]);
    __syncthreads();

    const uint4* s4 = (const uint4*)sbuf;               // 288 x 16B
    uint4* g4 = (uint4*)(g_act + (size_t)blockIdx.x * 2304);
#pragma unroll
    for (int i = tid; i < 288; i += 256) g4[i] = s4[i];
}

// ---------------------------------------------------------------------------
// Kernel 2: weight matrix.  W[o, i*9+0]=bw[o,i], [.. +1+q]=sw[o,i,q]
// ---------------------------------------------------------------------------
__global__ __launch_bounds__(256) void wconv_kernel(const float* __restrict__ bw,
                                                    const float* __restrict__ sw) {
    __shared__ __half sbuf[256 * 9];
    int tid = threadIdx.x;
    int idx = blockIdx.x * 256 + tid;   // o*1024 + i
    sbuf[tid * 9] = __float2half_rn(bw[idx]);
    const float4* sp = (const float4*)(sw + (size_t)idx * 8);
    float4 a = sp[0], b = sp[1];
    sbuf[tid * 9 + 1] = __float2half_rn(a.x); sbuf[tid * 9 + 2] = __float2half_rn(a.y);
    sbuf[tid * 9 + 3] = __float2half_rn(a.z); sbuf[tid * 9 + 4] = __float2half_rn(a.w);
    sbuf[tid * 9 + 5] = __float2half_rn(b.x); sbuf[tid * 9 + 6] = __float2half_rn(b.y);
    sbuf[tid * 9 + 7] = __float2half_rn(b.z); sbuf[tid * 9 + 8] = __float2half_rn(b.w);
    __syncthreads();

    const uint4* s4 = (const uint4*)sbuf;
    uint4* g4 = (uint4*)(g_w + (size_t)blockIdx.x * 2304);
#pragma unroll
    for (int i = tid; i < 288; i += 256) g4[i] = s4[i];
}

// ---------------------------------------------------------------------------
// Kernel 3: fp16 mma.sync GEMM  out[4096,1024] = Act @ W^T  (fp32 accumulate)
// CTA tile 128x128, 8 warps (2m x 4n), warp tile 64x32, m16n8k16 HMMA.
// 4-stage cp.async pipeline, smem row stride 40 halfs (conflict-free frags).
// ---------------------------------------------------------------------------
__device__ __forceinline__ void issue_stage(uint32_t sb, int stage, int it,
                                            int m0, int n0, int tid) {
    const int kk = it * CHUNK;
    const uint32_t sA = sb + stage * STAGE_BYTES;
    const uint32_t sB = sA + TILE_BYTES;
#pragma unroll
    for (int j = 0; j < 2; j++) {
        int id  = tid + j * 256;          // 0..511
        int row = id >> 2, c = id & 3;    // 128 rows x 4 chunks of 8 halfs
        const __half* ga = &g_act[(size_t)(m0 + row) * KDIM + kk + c * 8];
        asm volatile("cp.async.cg.shared.global [%0], [%1], 16;"
                     :: "r"(sA + (uint32_t)(row * SROW_H + c * 8) * 2), "l"(ga));
        const __half* gb = &g_w[(size_t)(n0 + row) * KDIM + kk + c * 8];
        asm volatile("cp.async.cg.shared.global [%0], [%1], 16;"
                     :: "r"(sB + (uint32_t)(row * SROW_H + c * 8) * 2), "l"(gb));
    }
}

__global__ __launch_bounds__(256, 1) void gemm_kernel(float* __restrict__ out) {
    extern __shared__ __align__(16) char smem[];
    const uint32_t sb = (uint32_t)__cvta_generic_to_shared(smem);
    const int tid = threadIdx.x;
    const int wid = tid >> 5, lane = tid & 31;
    const int g = lane >> 2, t = lane & 3;         // quad group / thread-in-group
    const int wm = wid >> 2, wn = wid & 3;         // 2 x 4 warp grid
    const int m0 = blockIdx.y * 128, n0 = blockIdx.x * 128;

    float acc[4][4][4];
#pragma unroll
    for (int i = 0; i < 4; i++)
#pragma unroll
        for (int j = 0; j < 4; j++)
#pragma unroll
            for (int r = 0; r < 4; r++) acc[i][j][r] = 0.f;

#pragma unroll
    for (int s = 0; s < STAGES - 1; s++) {
        issue_stage(sb, s, s, m0, n0, tid);
        asm volatile("cp.async.commit_group;");
    }

    const int aRow = wm * 64 + g;       // base A row for this lane
    const int bRow = wn * 32 + g;       // base B row for this lane

    for (int it = 0; it < ITERS; ++it) {
        asm volatile("cp.async.wait_group %0;" :: "n"(STAGES - 2));
        __syncthreads();
        if (it + STAGES - 1 < ITERS)
            issue_stage(sb, (it + STAGES - 1) % STAGES, it + STAGES - 1, m0, n0, tid);
        asm volatile("cp.async.commit_group;");

        const int buf = it % STAGES;
        const __half* As = (const __half*)(smem + buf * STAGE_BYTES);
        const __half* Bs = (const __half*)(smem + buf * STAGE_BYTES + TILE_BYTES);

#pragma unroll
        for (int kb = 0; kb < CHUNK; kb += 16) {
            uint32_t af[4][4], bf[4][2];
#pragma unroll
            for (int mi = 0; mi < 4; mi++) {
                int r = aRow + mi * 16;
                af[mi][0] = *(const uint32_t*)&As[r * SROW_H + kb + 2 * t];
                af[mi][1] = *(const uint32_t*)&As[(r + 8) * SROW_H + kb + 2 * t];
                af[mi][2] = *(const uint32_t*)&As[r * SROW_H + kb + 2 * t + 8];
                af[mi][3] = *(const uint32_t*)&As[(r + 8) * SROW_H + kb + 2 * t + 8];
            }
#pragma unroll
            for (int ni = 0; ni < 4; ni++) {
                int r = bRow + ni * 8;
                bf[ni][0] = *(const uint32_t*)&Bs[r * SROW_H + kb + 2 * t];
                bf[ni][1] = *(const uint32_t*)&Bs[r * SROW_H + kb + 2 * t + 8];
            }
#pragma unroll
            for (int mi = 0; mi < 4; mi++)
#pragma unroll
                for (int ni = 0; ni < 4; ni++) {
                    asm volatile(
                        "mma.sync.aligned.m16n8k16.row.col.f32.f16.f16.f32 "
                        "{%0,%1,%2,%3}, {%4,%5,%6,%7}, {%8,%9}, {%0,%1,%2,%3};"
                        : "+f"(acc[mi][ni][0]), "+f"(acc[mi][ni][1]),
                          "+f"(acc[mi][ni][2]), "+f"(acc[mi][ni][3])
                        : "r"(af[mi][0]), "r"(af[mi][1]),
                          "r"(af[mi][2]), "r"(af[mi][3]),
                          "r"(bf[ni][0]), "r"(bf[ni][1]));
                }
        }
    }

    // Epilogue: direct STG (each quad writes 32B contiguous segments)
#pragma unroll
    for (int mi = 0; mi < 4; mi++)
#pragma unroll
        for (int ni = 0; ni < 4; ni++) {
            int row = m0 + wm * 64 + mi * 16 + g;
            int col = n0 + wn * 32 + ni * 8 + 2 * t;
            float2 v0 = make_float2(acc[mi][ni][0], acc[mi][ni][1]);
            float2 v1 = make_float2(acc[mi][ni][2], acc[mi][ni][3]);
            *(float2*)&out[(size_t)row * OUTF + col]       = v0;
            *(float2*)&out[(size_t)(row + 8) * OUTF + col] = v1;
        }
}

// ---------------------------------------------------------------------------
extern "C" void kernel_launch(void* const* d_in, const int* in_sizes, int n_in,
                              void* d_out, int out_size) {
    const float* x    = (const float*)d_in[0];
    const float* bw   = (const float*)d_in[1];
    const float* sw   = (const float*)d_in[2];
    const float* grid = (const float*)d_in[3];
    float* out = (float*)d_out;

    cudaFuncSetAttribute(gemm_kernel, cudaFuncAttributeMaxDynamicSharedMemorySize,
                         SMEM_TOTAL);

    act_kernel<<<(BROWS * INF) / 256, 256>>>(x, grid);
    wconv_kernel<<<(OUTF * INF) / 256, 256>>>(bw, sw);
    gemm_kernel<<<dim3(OUTF / 128, BROWS / 128), 256, SMEM_TOTAL>>>(out);
}

// round 6
// speedup vs baseline: 1.8405x; 1.1825x over previous
#include <cuda_runtime.h>
#include <cuda_fp16.h>
#include <cstdint>

#define BROWS 4096
#define INF   1024
#define OUTF  1024
#define KDIM  9216          // INF * 9  (silu + 8 basis columns per input feature)
#define CHUNK 32            // k-chunk in halfs (64 B rows)
#define ITERS 288           // KDIM / CHUNK
#define STAGES 4
#define SROW_H 40           // smem row stride in halfs (80 B, conflict-free frags)

// GEMM: persistent 64x64 tiles, dynamic queue
#define TM 64
#define TN 64
#define NU_N (OUTF / TN)    // 16
#define NUNITS ((BROWS / TM) * NU_N)  // 1024
#define GTHREADS 128
#define TILE_BYTES_A (TM * SROW_H * 2)          // 5120
#define TILE_BYTES_B (TN * SROW_H * 2)          // 5120
#define STAGE_BYTES  (TILE_BYTES_A + TILE_BYTES_B)  // 10240
#define SMEM_TOTAL   (STAGES * STAGE_BYTES + 16)    // 40976

// Scratch (static device globals — no runtime allocation)
__device__ __align__(256) __half g_act[(size_t)BROWS * KDIM];  // [4096, 9216]
__device__ __align__(256) __half g_w[(size_t)OUTF * KDIM];     // [1024, 9216]
__device__ int g_ctr;

// ---------------------------------------------------------------------------
// Kernel 1: activation matrix.  Act[b, i*9+0] = silu(x), [.. +1+q] = basis_q(x)
// 8 elements/thread: denominator reciprocals hoisted (x-independent), FMA-only
// inner recurrence. Coalesced output via smem staging.
// ---------------------------------------------------------------------------
#define ACT_EPT 8
__global__ __launch_bounds__(256) void act_kernel(const float* __restrict__ x,
                                                  const float* __restrict__ grid) {
    __shared__ __half sbuf[256 * ACT_EPT * 9];
    const int tid = threadIdx.x;
    const size_t base = (size_t)blockIdx.x * (256 * ACT_EPT);

    float g[12];
#pragma unroll
    for (int j = 0; j < 12; j++) g[j] = __ldg(grid + j);

    // reciprocal denominators: rin[k-1][j] = 1/(g[j+k]-g[j]+1e-8), j <= 11-k
    float rin[3][11];
#pragma unroll
    for (int k = 1; k <= 3; k++)
#pragma unroll
        for (int j = 0; j + k <= 11; j++)
            rin[k - 1][j] = __fdividef(1.f, g[j + k] - g[j] + 1e-8f);

#pragma unroll
    for (int e = 0; e < ACT_EPT; e++) {
        const int loc = tid + e * 256;
        float xv = x[base + loc];

        float bas[11];
#pragma unroll
        for (int j = 0; j < 11; j++)
            bas[j] = (xv >= g[j] && xv < g[j + 1]) ? 1.f : 0.f;
#pragma unroll
        for (int k = 1; k <= 3; k++) {
#pragma unroll
            for (int j = 0; j + k <= 10; j++) {
                float left  = (xv - g[j]) * rin[k - 1][j];
                float right = (g[j + k + 1] - xv) * rin[k - 1][j + 1];
                bas[j] = left * bas[j] + right * bas[j + 1];
            }
        }
        float s = xv * __frcp_rn(1.f + __expf(-xv));

        __half* o = sbuf + loc * 9;
        o[0] = __float2half_rn(s);
#pragma unroll
        for (int q = 0; q < 8; q++) o[1 + q] = __float2half_rn(bas[q]);
    }
    __syncthreads();

    const uint4* s4 = (const uint4*)sbuf;                 // 1152 x 16B
    uint4* g4 = (uint4*)(g_act + base * 9);
#pragma unroll
    for (int i = 0; i < 9; i++) g4[tid + i * 256] = s4[tid + i * 256];
}

// ---------------------------------------------------------------------------
// Kernel 2: weight matrix.  W[o, i*9+0]=bw[o,i], [.. +1+q]=sw[o,i,q]
// ---------------------------------------------------------------------------
__global__ __launch_bounds__(256) void wconv_kernel(const float* __restrict__ bw,
                                                    const float* __restrict__ sw) {
    __shared__ __half sbuf[256 * 9];
    int tid = threadIdx.x;
    if (blockIdx.x == 0 && tid == 0) g_ctr = 0;   // reset GEMM work queue
    int idx = blockIdx.x * 256 + tid;   // o*1024 + i
    sbuf[tid * 9] = __float2half_rn(bw[idx]);
    const float4* sp = (const float4*)(sw + (size_t)idx * 8);
    float4 a = sp[0], b = sp[1];
    sbuf[tid * 9 + 1] = __float2half_rn(a.x); sbuf[tid * 9 + 2] = __float2half_rn(a.y);
    sbuf[tid * 9 + 3] = __float2half_rn(a.z); sbuf[tid * 9 + 4] = __float2half_rn(a.w);
    sbuf[tid * 9 + 5] = __float2half_rn(b.x); sbuf[tid * 9 + 6] = __float2half_rn(b.y);
    sbuf[tid * 9 + 7] = __float2half_rn(b.z); sbuf[tid * 9 + 8] = __float2half_rn(b.w);
    __syncthreads();

    const uint4* s4 = (const uint4*)sbuf;
    uint4* g4 = (uint4*)(g_w + (size_t)blockIdx.x * 2304);
#pragma unroll
    for (int i = tid; i < 288; i += 256) g4[i] = s4[i];
}

// ---------------------------------------------------------------------------
// Kernel 3: fp16 mma.sync GEMM  out[4096,1024] = Act @ W^T  (fp32 accumulate)
// Persistent CTAs (296 = 2/SM), dynamic 64x64 tile queue (1024 units).
// 4 warps (2m x 2n), warp tile 32x32, m16n8k16 HMMA, 4-stage cp.async.
// ---------------------------------------------------------------------------
__device__ __forceinline__ void issue_stage(uint32_t sb, int stage, int it,
                                            int m0, int n0, int tid) {
    const int kk = it * CHUNK;
    const uint32_t sA = sb + stage * STAGE_BYTES;
    const uint32_t sB = sA + TILE_BYTES_A;
#pragma unroll
    for (int j = 0; j < 2; j++) {                 // 64 rows x 4 chunks = 256 copies
        int id  = tid + j * GTHREADS;             // 0..255
        int row = id >> 2, c = id & 3;
        const __half* ga = &g_act[(size_t)(m0 + row) * KDIM + kk + c * 8];
        asm volatile("cp.async.cg.shared.global [%0], [%1], 16;"
                     :: "r"(sA + (uint32_t)(row * SROW_H + c * 8) * 2), "l"(ga));
        const __half* gb = &g_w[(size_t)(n0 + row) * KDIM + kk + c * 8];
        asm volatile("cp.async.cg.shared.global [%0], [%1], 16;"
                     :: "r"(sB + (uint32_t)(row * SROW_H + c * 8) * 2), "l"(gb));
    }
}

__global__ __launch_bounds__(GTHREADS, 2) void gemm_kernel(float* __restrict__ out) {
    extern __shared__ __align__(16) char smem[];
    const uint32_t sb = (uint32_t)__cvta_generic_to_shared(smem);
    int* s_unit = (int*)(smem + STAGES * STAGE_BYTES);
    const int tid = threadIdx.x;
    const int wid = tid >> 5, lane = tid & 31;
    const int g = lane >> 2, t = lane & 3;         // quad group / thread-in-group
    const int wm = wid >> 1, wn = wid & 1;         // 2 x 2 warp grid

    for (;;) {
        if (tid == 0) *s_unit = atomicAdd(&g_ctr, 1);
        __syncthreads();
        const int u = *s_unit;
        if (u >= NUNITS) break;
        const int m0 = (u >> 4) * TM;   // consecutive units share the A strip
        const int n0 = (u & 15) * TN;

        float acc[2][4][4];
#pragma unroll
        for (int i = 0; i < 2; i++)
#pragma unroll
            for (int j = 0; j < 4; j++)
#pragma unroll
                for (int r = 0; r < 4; r++) acc[i][j][r] = 0.f;

#pragma unroll
        for (int s = 0; s < STAGES - 1; s++) {
            issue_stage(sb, s, s, m0, n0, tid);
            asm volatile("cp.async.commit_group;");
        }

        const int aRow = wm * 32 + g;
        const int bRow = wn * 32 + g;

        for (int it = 0; it < ITERS; ++it) {
            asm volatile("cp.async.wait_group %0;" :: "n"(STAGES - 2));
            __syncthreads();
            if (it + STAGES - 1 < ITERS)
                issue_stage(sb, (it + STAGES - 1) % STAGES, it + STAGES - 1, m0, n0, tid);
            asm volatile("cp.async.commit_group;");

            const int buf = it % STAGES;
            const __half* As = (const __half*)(smem + buf * STAGE_BYTES);
            const __half* Bs = (const __half*)(smem + buf * STAGE_BYTES + TILE_BYTES_A);

#pragma unroll
            for (int kb = 0; kb < CHUNK; kb += 16) {
                uint32_t af[2][4], bf[4][2];
#pragma unroll
                for (int mi = 0; mi < 2; mi++) {
                    int r = aRow + mi * 16;
                    af[mi][0] = *(const uint32_t*)&As[r * SROW_H + kb + 2 * t];
                    af[mi][1] = *(const uint32_t*)&As[(r + 8) * SROW_H + kb + 2 * t];
                    af[mi][2] = *(const uint32_t*)&As[r * SROW_H + kb + 2 * t + 8];
                    af[mi][3] = *(const uint32_t*)&As[(r + 8) * SROW_H + kb + 2 * t + 8];
                }
#pragma unroll
                for (int ni = 0; ni < 4; ni++) {
                    int r = bRow + ni * 8;
                    bf[ni][0] = *(const uint32_t*)&Bs[r * SROW_H + kb + 2 * t];
                    bf[ni][1] = *(const uint32_t*)&Bs[r * SROW_H + kb + 2 * t + 8];
                }
#pragma unroll
                for (int mi = 0; mi < 2; mi++)
#pragma unroll
                    for (int ni = 0; ni < 4; ni++) {
                        asm volatile(
                            "mma.sync.aligned.m16n8k16.row.col.f32.f16.f16.f32 "
                            "{%0,%1,%2,%3}, {%4,%5,%6,%7}, {%8,%9}, {%0,%1,%2,%3};"
                            : "+f"(acc[mi][ni][0]), "+f"(acc[mi][ni][1]),
                              "+f"(acc[mi][ni][2]), "+f"(acc[mi][ni][3])
                            : "r"(af[mi][0]), "r"(af[mi][1]),
                              "r"(af[mi][2]), "r"(af[mi][3]),
                              "r"(bf[ni][0]), "r"(bf[ni][1]));
                    }
            }
        }
        asm volatile("cp.async.wait_group 0;");

        // Epilogue: direct STG (each quad writes 8B contiguous, 32B per quad-row)
#pragma unroll
        for (int mi = 0; mi < 2; mi++)
#pragma unroll
            for (int ni = 0; ni < 4; ni++) {
                int row = m0 + wm * 32 + mi * 16 + g;
                int col = n0 + wn * 32 + ni * 8 + 2 * t;
                float2 v0 = make_float2(acc[mi][ni][0], acc[mi][ni][1]);
                float2 v1 = make_float2(acc[mi][ni][2], acc[mi][ni][3]);
                *(float2*)&out[(size_t)row * OUTF + col]       = v0;
                *(float2*)&out[(size_t)(row + 8) * OUTF + col] = v1;
            }
        // next-unit grab barrier also protects smem stage reuse
    }
}

// ---------------------------------------------------------------------------
extern "C" void kernel_launch(void* const* d_in, const int* in_sizes, int n_in,
                              void* d_out, int out_size) {
    const float* x    = (const float*)d_in[0];
    const float* bw   = (const float*)d_in[1];
    const float* sw   = (const float*)d_in[2];
    const float* grid = (const float*)d_in[3];
    float* out = (float*)d_out;

    cudaFuncSetAttribute(gemm_kernel, cudaFuncAttributeMaxDynamicSharedMemorySize,
                         SMEM_TOTAL);

    act_kernel<<<(BROWS * INF) / (256 * ACT_EPT), 256>>>(x, grid);
    wconv_kernel<<<(OUTF * INF) / 256, 256>>>(bw, sw);
    gemm_kernel<<<296, GTHREADS, SMEM_TOTAL>>>(out);
}

// round 8
// speedup vs baseline: 2.2893x; 1.2438x over previous
#include <cuda_runtime.h>
#include <cuda_fp16.h>
#include <cstdint>

#define BROWS 4096
#define INF   1024
#define OUTF  1024
#define KDIM  9216          // INF * 9  (silu + 8 basis columns per input feature)

// GEMM config: persistent, 128x64 tiles, split-K=4, dynamic queue
#define TMd 128
#define TNd 64
#define KSPLIT 4
#define KPER  (KDIM / KSPLIT)   // 2304
#define CHUNK 64                // k-chunk in halfs
#define ITERSU (KPER / CHUNK)   // 36
#define STAGES 3
#define SROW_H 72               // smem row stride in halfs (144 B, conflict-free)
#define A_BYTES (TMd * SROW_H * 2)        // 18432
#define B_BYTES (TNd * SROW_H * 2)        // 9216
#define STAGE_BYTES (A_BYTES + B_BYTES)   // 27648
#define SMEM_TOTAL (STAGES * STAGE_BYTES + 16)  // 82960
#define NUNITS ((BROWS / TMd) * (OUTF / TNd) * KSPLIT)  // 2048
#define GCTAS 296
#define GTHREADS 128

// Scratch (static device globals — no runtime allocation)
__device__ __align__(256) __half g_act[(size_t)BROWS * KDIM];   // 75 MB
__device__ __align__(256) __half g_w[(size_t)OUTF * KDIM];      // 19 MB
__device__ __align__(256) float  g_part[(size_t)KSPLIT * BROWS * OUTF];  // 67 MB
__device__ int g_ctr;

// ---------------------------------------------------------------------------
// Kernel 1: activation matrix — closed-form uniform cubic B-spline.
// Act[b, i*9+0]=silu(x); of the 8 basis cols only 4 (q=j-3..j) are nonzero.
// ---------------------------------------------------------------------------
#define ACT_EPT 8
__global__ __launch_bounds__(256) void act_kernel(const float* __restrict__ x,
                                                  const float* __restrict__ grid) {
    __shared__ __half sbuf[256 * ACT_EPT * 9];
    const int tid = threadIdx.x;
    const size_t base = (size_t)blockIdx.x * (256 * ACT_EPT);

    const float g0   = __ldg(grid);
    const float invh = 11.f / (__ldg(grid + 11) - g0);

#pragma unroll
    for (int e = 0; e < ACT_EPT; e++) {
        const int loc = tid + e * 256;
        float xv = x[base + loc];

        float u = (xv - g0) * invh;
        float jf = floorf(u);
        int j = (int)jf;
        j = j < 0 ? 0 : (j > 10 ? 10 : j);
        float f = u - (float)j;
        float f2 = f * f, f3 = f2 * f;
        float om = 1.f - f;
        float p0 = f3 * (1.f / 6.f);                    // basis q = j     (piece 0)
        float p3 = om * om * om * (1.f / 6.f);          // basis q = j-3   (piece 3)
        float p2 = 0.5f * f3 - f2 + (4.f / 6.f);        // basis q = j-2   (piece 2)
        float p1 = 1.f - p0 - p2 - p3;                  // basis q = j-1   (piece 1)

        float s = xv * __frcp_rn(1.f + __expf(-xv));    // silu

        __half* o = sbuf + loc * 9;
        o[0] = __float2half_rn(s);
        const __half hz = __float2half_rn(0.f);
#pragma unroll
        for (int q = 0; q < 8; q++) o[1 + q] = hz;
        if (j < 8)               o[1 + j]     = __float2half_rn(p0);
        if (j >= 1 && j - 1 < 8) o[1 + j - 1] = __float2half_rn(p1);
        if (j >= 2 && j - 2 < 8) o[1 + j - 2] = __float2half_rn(p2);
        if (j >= 3 && j - 3 < 8) o[1 + j - 3] = __float2half_rn(p3);
    }
    __syncthreads();

    const uint4* s4 = (const uint4*)sbuf;                 // 2304 x 16B
    uint4* g4 = (uint4*)(g_act + base * 9);
#pragma unroll
    for (int i = tid; i < 2304; i += 256) g4[i] = s4[i];
}

// ---------------------------------------------------------------------------
// Kernel 2: weight matrix.  W[o, i*9+0]=bw[o,i], [.. +1+q]=sw[o,i,q]
// ---------------------------------------------------------------------------
__global__ __launch_bounds__(256) void wconv_kernel(const float* __restrict__ bw,
                                                    const float* __restrict__ sw) {
    __shared__ __half sbuf[256 * 9];
    int tid = threadIdx.x;
    if (blockIdx.x == 0 && tid == 0) g_ctr = 0;   // reset GEMM work queue
    int idx = blockIdx.x * 256 + tid;   // o*1024 + i
    sbuf[tid * 9] = __float2half_rn(bw[idx]);
    const float4* sp = (const float4*)(sw + (size_t)idx * 8);
    float4 a = sp[0], b = sp[1];
    sbuf[tid * 9 + 1] = __float2half_rn(a.x); sbuf[tid * 9 + 2] = __float2half_rn(a.y);
    sbuf[tid * 9 + 3] = __float2half_rn(a.z); sbuf[tid * 9 + 4] = __float2half_rn(a.w);
    sbuf[tid * 9 + 5] = __float2half_rn(b.x); sbuf[tid * 9 + 6] = __float2half_rn(b.y);
    sbuf[tid * 9 + 7] = __float2half_rn(b.z); sbuf[tid * 9 + 8] = __float2half_rn(b.w);
    __syncthreads();

    const uint4* s4 = (const uint4*)sbuf;
    uint4* g4 = (uint4*)(g_w + (size_t)blockIdx.x * 2304);
#pragma unroll
    for (int i = tid; i < 288; i += 256) g4[i] = s4[i];
}

// ---------------------------------------------------------------------------
// Kernel 3: fp16 mma.sync GEMM, persistent split-K.
// 296 CTAs (2/SM), 2048 units (32m x 16n x 4k), 4 warps (2x2), warp 64x32.
// ---------------------------------------------------------------------------
__device__ __forceinline__ void issue_stage(uint32_t sb, int stage, int it,
                                            int m0, int n0, int kb0, int tid) {
    const int kk = kb0 + it * CHUNK;
    const uint32_t sA = sb + stage * STAGE_BYTES;
    const uint32_t sB = sA + A_BYTES;
#pragma unroll
    for (int j = 0; j < 12; j++) {            // 192 rows x 8 chunks = 1536 copies
        int id  = tid + j * GTHREADS;         // 0..1535
        int row = id >> 3, c = id & 7;
        if (row < TMd) {
            const __half* ga = &g_act[(size_t)(m0 + row) * KDIM + kk + c * 8];
            asm volatile("cp.async.cg.shared.global [%0], [%1], 16;"
                         :: "r"(sA + (uint32_t)(row * SROW_H + c * 8) * 2), "l"(ga));
        } else {
            int r2 = row - TMd;
            const __half* gb = &g_w[(size_t)(n0 + r2) * KDIM + kk + c * 8];
            asm volatile("cp.async.cg.shared.global [%0], [%1], 16;"
                         :: "r"(sB + (uint32_t)(r2 * SROW_H + c * 8) * 2), "l"(gb));
        }
    }
}

__global__ __launch_bounds__(GTHREADS, 2) void gemm_kernel() {
    extern __shared__ __align__(16) char smem[];
    const uint32_t sb = (uint32_t)__cvta_generic_to_shared(smem);
    int* s_unit = (int*)(smem + STAGES * STAGE_BYTES);
    const int tid = threadIdx.x;
    const int wid = tid >> 5, lane = tid & 31;
    const int g = lane >> 2, t = lane & 3;
    const int wm = wid >> 1, wn = wid & 1;     // 2 x 2 warp grid

    for (;;) {
        if (tid == 0) *s_unit = atomicAdd(&g_ctr, 1);
        __syncthreads();
        const int u = *s_unit;
        if (u >= NUNITS) break;
        const int m0  = (u >> 6) * TMd;         // 16 consecutive units share A strip
        const int ks  = (u >> 4) & 3;
        const int n0  = (u & 15) * TNd;
        const int kb0 = ks * KPER;

        float acc[4][4][4];
#pragma unroll
        for (int i = 0; i < 4; i++)
#pragma unroll
            for (int jj = 0; jj < 4; jj++)
#pragma unroll
                for (int r = 0; r < 4; r++) acc[i][jj][r] = 0.f;

#pragma unroll
        for (int s = 0; s < STAGES - 1; s++) {
            issue_stage(sb, s, s, m0, n0, kb0, tid);
            asm volatile("cp.async.commit_group;");
        }

        const int aRow = wm * 64 + g;
        const int bRow = wn * 32 + g;

        for (int it = 0; it < ITERSU; ++it) {
            asm volatile("cp.async.wait_group %0;" :: "n"(STAGES - 2));
            __syncthreads();
            if (it + STAGES - 1 < ITERSU)
                issue_stage(sb, (it + STAGES - 1) % STAGES, it + STAGES - 1,
                            m0, n0, kb0, tid);
            asm volatile("cp.async.commit_group;");

            const int buf = it % STAGES;
            const __half* As = (const __half*)(smem + buf * STAGE_BYTES);
            const __half* Bs = (const __half*)(smem + buf * STAGE_BYTES + A_BYTES);

#pragma unroll
            for (int kb = 0; kb < CHUNK; kb += 16) {
                uint32_t af[4][4], bf[4][2];
#pragma unroll
                for (int mi = 0; mi < 4; mi++) {
                    int r = aRow + mi * 16;
                    af[mi][0] = *(const uint32_t*)&As[r * SROW_H + kb + 2 * t];
                    af[mi][1] = *(const uint32_t*)&As[(r + 8) * SROW_H + kb + 2 * t];
                    af[mi][2] = *(const uint32_t*)&As[r * SROW_H + kb + 2 * t + 8];
                    af[mi][3] = *(const uint32_t*)&As[(r + 8) * SROW_H + kb + 2 * t + 8];
                }
#pragma unroll
                for (int ni = 0; ni < 4; ni++) {
                    int r = bRow + ni * 8;
                    bf[ni][0] = *(const uint32_t*)&Bs[r * SROW_H + kb + 2 * t];
                    bf[ni][1] = *(const uint32_t*)&Bs[r * SROW_H + kb + 2 * t + 8];
                }
#pragma unroll
                for (int mi = 0; mi < 4; mi++)
#pragma unroll
                    for (int ni = 0; ni < 4; ni++) {
                        asm volatile(
                            "mma.sync.aligned.m16n8k16.row.col.f32.f16.f16.f32 "
                            "{%0,%1,%2,%3}, {%4,%5,%6,%7}, {%8,%9}, {%0,%1,%2,%3};"
                            : "+f"(acc[mi][ni][0]), "+f"(acc[mi][ni][1]),
                              "+f"(acc[mi][ni][2]), "+f"(acc[mi][ni][3])
                            : "r"(af[mi][0]), "r"(af[mi][1]),
                              "r"(af[mi][2]), "r"(af[mi][3]),
                              "r"(bf[ni][0]), "r"(bf[ni][1]));
                    }
            }
        }

        // Epilogue: write partial tile to g_part[ks]
        float* part = g_part + (size_t)ks * BROWS * OUTF;
#pragma unroll
        for (int mi = 0; mi < 4; mi++)
#pragma unroll
            for (int ni = 0; ni < 4; ni++) {
                int row = m0 + wm * 64 + mi * 16 + g;
                int col = n0 + wn * 32 + ni * 8 + 2 * t;
                float2 v0 = make_float2(acc[mi][ni][0], acc[mi][ni][1]);
                float2 v1 = make_float2(acc[mi][ni][2], acc[mi][ni][3]);
                *(float2*)&part[(size_t)row * OUTF + col]       = v0;
                *(float2*)&part[(size_t)(row + 8) * OUTF + col] = v1;
            }
        // next-unit barrier protects smem stage reuse
    }
}

// ---------------------------------------------------------------------------
// Kernel 4: reduce partials -> out
// ---------------------------------------------------------------------------
#define RED_N ((BROWS * OUTF) / 4)   // float4 count = 1048576
__global__ __launch_bounds__(256) void reduce_kernel(float* __restrict__ out) {
    int i = blockIdx.x * 256 + threadIdx.x;
    const float4* p = (const float4*)g_part;
    float4 a = p[i];
    float4 b = p[i + RED_N];
    float4 c = p[i + 2 * RED_N];
    float4 d = p[i + 3 * RED_N];
    float4 r;
    r.x = (a.x + b.x) + (c.x + d.x);
    r.y = (a.y + b.y) + (c.y + d.y);
    r.z = (a.z + b.z) + (c.z + d.z);
    r.w = (a.w + b.w) + (c.w + d.w);
    ((float4*)out)[i] = r;
}

// ---------------------------------------------------------------------------
extern "C" void kernel_launch(void* const* d_in, const int* in_sizes, int n_in,
                              void* d_out, int out_size) {
    const float* x    = (const float*)d_in[0];
    const float* bw   = (const float*)d_in[1];
    const float* sw   = (const float*)d_in[2];
    const float* grid = (const float*)d_in[3];
    float* out = (float*)d_out;

    cudaFuncSetAttribute(gemm_kernel, cudaFuncAttributeMaxDynamicSharedMemorySize,
                         SMEM_TOTAL);

    act_kernel<<<(BROWS * INF) / (256 * ACT_EPT), 256>>>(x, grid);
    wconv_kernel<<<(OUTF * INF) / 256, 256>>>(bw, sw);
    gemm_kernel<<<GCTAS, GTHREADS, SMEM_TOTAL>>>();
    reduce_kernel<<<RED_N / 256, 256>>>(out);
}